// round 12
// baseline (speedup 1.0000x reference)
#include <cuda_runtime.h>
#include <cstdint>

// Problem constants
#define NNv 5
#define NACTv 8
#define ROWS 32768
#define CHUNKS 8192               // chunks of 4 rows
#define ROW_F 5120                // floats per (b,j) row of y

#define NTHREADS 640              // 20 warps: 14 streamers + 6 MLP/epilogue producers
#define NSTREAM 14
#define NMLP 6
#define GRID 152
#define MAXK 56                   // max chunks per block (8192/152 -> 54) padded

// smem layout, offsets in floats
#define OFF_WE0   0          // 128*128 = 16384
#define OFF_WE1   16384      // 128*32  = 4096
#define OFF_W1    20480      // 32*32
#define OFF_W2    21504
#define OFF_W3    22528
#define OFF_W4P   23552      // [8][32] fused W4@Wp
#define OFF_W34   23808      // [32][8] (W3 @ W4p^T)
#define OFF_BE0   24064      // 128
#define OFF_BE1   24192      // 32
#define OFF_B1    24224
#define OFF_B2    24256
#define OFF_B3    24288
#define OFF_B4P   24320      // 8 (b4@Wp+bp), pad 32
#define OFF_B34P  24352      // 8, pad 32
#define OFF_YS    24384      // 56 slots * 20 floats = 1120
#define OFF_YSFLG 25504      // 56 ints
#define OFF_XBUF  25568      // 6 mlp warps * 512 = 3072
#define SMEM_FLOATS 28640
#define SMEM_BYTES (SMEM_FLOATS * 4)   // ~114.6 KB

__device__ __forceinline__ float warpsum(float v) {
    v += __shfl_xor_sync(0xffffffffu, v, 16);
    v += __shfl_xor_sync(0xffffffffu, v, 8);
    v += __shfl_xor_sync(0xffffffffu, v, 4);
    v += __shfl_xor_sync(0xffffffffu, v, 2);
    v += __shfl_xor_sync(0xffffffffu, v, 1);
    return v;
}

__device__ __forceinline__ void fma4(float4& a, float s, const float4& w) {
    a.x = fmaf(s, w.x, a.x);
    a.y = fmaf(s, w.y, a.y);
    a.z = fmaf(s, w.z, a.z);
    a.w = fmaf(s, w.w, a.w);
}

__device__ __forceinline__ float r4(const float4& v) {
    return (v.x + v.y) + (v.z + v.w);
}

__global__ __launch_bounds__(NTHREADS, 1) void fused_kernel(
    const float* __restrict__ x,
    const float* __restrict__ y,
    const float* __restrict__ We0, const float* __restrict__ be0,
    const float* __restrict__ We1, const float* __restrict__ be1,
    const float* __restrict__ W1, const float* __restrict__ b1,
    const float* __restrict__ W2, const float* __restrict__ b2,
    const float* __restrict__ W3, const float* __restrict__ b3,
    const float* __restrict__ W4, const float* __restrict__ b4,
    const float* __restrict__ Wp, const float* __restrict__ bp,
    float* __restrict__ out)
{
    extern __shared__ float sm[];
    const int tid  = threadIdx.x;
    const int lane = tid & 31;
    const int w    = tid >> 5;
    const int b    = blockIdx.x;

    // ---- stage A: weights into smem + first-level fusions ----
    for (int i = tid; i < 16384; i += NTHREADS) sm[OFF_WE0 + i] = We0[i];
    for (int i = tid; i < 4096;  i += NTHREADS) sm[OFF_WE1 + i] = We1[i];
    for (int i = tid; i < 1024;  i += NTHREADS) {
        sm[OFF_W1 + i] = W1[i];
        sm[OFF_W2 + i] = W2[i];
        sm[OFF_W3 + i] = W3[i];
    }
    if (tid < 256) {
        const int a = tid >> 5, e = tid & 31;
        float acc = 0.f;
        #pragma unroll 8
        for (int k = 0; k < 32; k++)
            acc = fmaf(W4[e * 32 + k], Wp[k * NACTv + a], acc);
        sm[OFF_W4P + a * 32 + e] = acc;
    }
    if (tid < 128) sm[OFF_BE0 + tid] = be0[tid];
    if (tid < 32) {
        sm[OFF_BE1 + tid] = be1[tid];
        sm[OFF_B1 + tid] = b1[tid];
        sm[OFF_B2 + tid] = b2[tid];
        sm[OFF_B3 + tid] = b3[tid];
        if (tid < 8) {
            float acc = bp[tid];
            #pragma unroll 8
            for (int k = 0; k < 32; k++)
                acc = fmaf(b4[k], Wp[k * NACTv + tid], acc);
            sm[OFF_B4P + tid] = acc;
        }
    }
    int* ysflg = (int*)(sm + OFF_YSFLG);
    if (tid < MAXK) ysflg[tid] = 0;
    __syncthreads();

    // ---- stage B: second-level fusions ----
    if (tid < 256) {
        const int e = tid >> 3, a = tid & 7;
        float acc = 0.f;
        #pragma unroll 8
        for (int d = 0; d < 32; d++)
            acc = fmaf(sm[OFF_W3 + e * 32 + d], sm[OFF_W4P + a * 32 + d], acc);
        sm[OFF_W34 + e * 8 + a] = acc;
    }
    if (tid < 8) {
        float acc = sm[OFF_B4P + tid];
        #pragma unroll 8
        for (int d = 0; d < 32; d++)
            acc = fmaf(sm[OFF_B3 + d], sm[OFF_W4P + tid * 32 + d], acc);
        sm[OFF_B34P + tid] = acc;
    }
    __syncthreads();

    volatile int* vflg = (volatile int*)ysflg;

    if (w < NSTREAM) {
        // ============ STREAMER warps: pure y streaming, NO waits ============
        // Explicit 10-load batches so ptxas front-batches LDGs (in-flight depth
        // guaranteed ~10 per warp instead of 1-2 with interleaved accumulate).
        for (int k = w; k < MAXK; k += NSTREAM) {
            const int gchunk = b + GRID * k;
            if (gchunk >= CHUNKS) break;
            const int row0 = gchunk * 4;

            const float4* yb = (const float4*)(y + (size_t)row0 * ROW_F) + lane;
            float* dst = sm + OFF_YS + k * 20;

            #pragma unroll
            for (int r = 0; r < 4; r++) {
                float s0 = 0.f, s1 = 0.f, s2 = 0.f, s3 = 0.f, s4 = 0.f;
                #pragma unroll
                for (int half = 0; half < 4; half++) {
                    // 10 independent loads, no consumers in between
                    float4 t0, t1, t2, t3, t4, t5, t6, t7, t8, t9;
                    const float4* p = yb + (size_t)r * 1280 + half * 64;
                    t0 = __ldcs(p + 0 * 256);
                    t1 = __ldcs(p + 0 * 256 + 32);
                    t2 = __ldcs(p + 1 * 256);
                    t3 = __ldcs(p + 1 * 256 + 32);
                    t4 = __ldcs(p + 2 * 256);
                    t5 = __ldcs(p + 2 * 256 + 32);
                    t6 = __ldcs(p + 3 * 256);
                    t7 = __ldcs(p + 3 * 256 + 32);
                    t8 = __ldcs(p + 4 * 256);
                    t9 = __ldcs(p + 4 * 256 + 32);
                    s0 += r4(t0) + r4(t1);
                    s1 += r4(t2) + r4(t3);
                    s2 += r4(t4) + r4(t5);
                    s3 += r4(t6) + r4(t7);
                    s4 += r4(t8) + r4(t9);
                }
                s0 = warpsum(s0);
                s1 = warpsum(s1);
                s2 = warpsum(s2);
                s3 = warpsum(s3);
                s4 = warpsum(s4);
                if (lane == 0) {
                    dst[r * 5 + 0] = s0;
                    dst[r * 5 + 1] = s1;
                    dst[r * 5 + 2] = s2;
                    dst[r * 5 + 3] = s3;
                    dst[r * 5 + 4] = s4;
                }
            }
            __syncwarp();
            if (lane == 0) {
                __threadfence_block();
                vflg[k] = 1;
            }
        }
    } else {
        // ========= PRODUCER warps: MLP + full epilogue per chunk =========
        const int mw = w - NSTREAM;
        const float4* We0s4 = (const float4*)(sm + OFF_WE0);
        const float4* be0s4 = (const float4*)(sm + OFF_BE0);
        float4* xb4 = (float4*)(sm + OFF_XBUF) + mw * 128;
        const float b1v  = sm[OFF_B1 + lane];
        const float b2v  = sm[OFF_B2 + lane];
        const float be1v = sm[OFF_BE1 + lane];
        const float b34pv = sm[OFF_B34P + (lane & 7)];
        const int la8 = lane & 7;

        for (int k = mw; k < MAXK; k += NMLP) {
            const int gchunk = b + GRID * k;
            if (gchunk >= CHUNKS) break;
            const int row0 = gchunk * 4;

            // stage x
            #pragma unroll
            for (int r = 0; r < 4; r++)
                xb4[r * 32 + lane] = __ldcs(((const float4*)(x)) + (size_t)(row0 + r) * 32 + lane);
            __syncwarp();

            // layer 0
            float4 acc0 = be0s4[lane], acc1 = acc0, acc2 = acc0, acc3 = acc0;
            #pragma unroll 8
            for (int k4 = 0; k4 < 32; k4++) {
                float4 w0 = We0s4[(k4 * 4 + 0) * 32 + lane];
                float4 w1 = We0s4[(k4 * 4 + 1) * 32 + lane];
                float4 w2 = We0s4[(k4 * 4 + 2) * 32 + lane];
                float4 w3 = We0s4[(k4 * 4 + 3) * 32 + lane];
                float4 xk;
                xk = xb4[0 * 32 + k4];
                fma4(acc0, xk.x, w0); fma4(acc0, xk.y, w1); fma4(acc0, xk.z, w2); fma4(acc0, xk.w, w3);
                xk = xb4[1 * 32 + k4];
                fma4(acc1, xk.x, w0); fma4(acc1, xk.y, w1); fma4(acc1, xk.z, w2); fma4(acc1, xk.w, w3);
                xk = xb4[2 * 32 + k4];
                fma4(acc2, xk.x, w0); fma4(acc2, xk.y, w1); fma4(acc2, xk.z, w2); fma4(acc2, xk.w, w3);
                xk = xb4[3 * 32 + k4];
                fma4(acc3, xk.x, w0); fma4(acc3, xk.y, w1); fma4(acc3, xk.z, w2); fma4(acc3, xk.w, w3);
            }
            __syncwarp();
            acc0.x = fmaxf(acc0.x, 0.f); acc0.y = fmaxf(acc0.y, 0.f); acc0.z = fmaxf(acc0.z, 0.f); acc0.w = fmaxf(acc0.w, 0.f);
            acc1.x = fmaxf(acc1.x, 0.f); acc1.y = fmaxf(acc1.y, 0.f); acc1.z = fmaxf(acc1.z, 0.f); acc1.w = fmaxf(acc1.w, 0.f);
            acc2.x = fmaxf(acc2.x, 0.f); acc2.y = fmaxf(acc2.y, 0.f); acc2.z = fmaxf(acc2.z, 0.f); acc2.w = fmaxf(acc2.w, 0.f);
            acc3.x = fmaxf(acc3.x, 0.f); acc3.y = fmaxf(acc3.y, 0.f); acc3.z = fmaxf(acc3.z, 0.f); acc3.w = fmaxf(acc3.w, 0.f);
            xb4[0 * 32 + lane] = acc0;
            xb4[1 * 32 + lane] = acc1;
            xb4[2 * 32 + lane] = acc2;
            xb4[3 * 32 + lane] = acc3;
            __syncwarp();

            // layer 1
            float a1_0 = be1v, a1_1 = be1v, a1_2 = be1v, a1_3 = be1v;
            #pragma unroll 8
            for (int k4 = 0; k4 < 32; k4++) {
                float w0 = sm[OFF_WE1 + (k4 * 4 + 0) * 32 + lane];
                float w1 = sm[OFF_WE1 + (k4 * 4 + 1) * 32 + lane];
                float w2 = sm[OFF_WE1 + (k4 * 4 + 2) * 32 + lane];
                float w3 = sm[OFF_WE1 + (k4 * 4 + 3) * 32 + lane];
                float4 hk;
                hk = xb4[0 * 32 + k4];
                a1_0 = fmaf(hk.x, w0, a1_0); a1_0 = fmaf(hk.y, w1, a1_0); a1_0 = fmaf(hk.z, w2, a1_0); a1_0 = fmaf(hk.w, w3, a1_0);
                hk = xb4[1 * 32 + k4];
                a1_1 = fmaf(hk.x, w0, a1_1); a1_1 = fmaf(hk.y, w1, a1_1); a1_1 = fmaf(hk.z, w2, a1_1); a1_1 = fmaf(hk.w, w3, a1_1);
                hk = xb4[2 * 32 + k4];
                a1_2 = fmaf(hk.x, w0, a1_2); a1_2 = fmaf(hk.y, w1, a1_2); a1_2 = fmaf(hk.z, w2, a1_2); a1_2 = fmaf(hk.w, w3, a1_2);
                hk = xb4[3 * 32 + k4];
                a1_3 = fmaf(hk.x, w0, a1_3); a1_3 = fmaf(hk.y, w1, a1_3); a1_3 = fmaf(hk.z, w2, a1_3); a1_3 = fmaf(hk.w, w3, a1_3);
            }
            float h[4];
            h[0] = fmaxf(a1_0, 0.f); h[1] = fmaxf(a1_1, 0.f);
            h[2] = fmaxf(a1_2, 0.f); h[3] = fmaxf(a1_3, 0.f);

            // g1/g2 per lane-dim; q on lanes 0..7
            float g1[4], g2[4], q[4];
            #pragma unroll
            for (int r = 0; r < 4; r++) { g1[r] = b1v; g2[r] = 0.f; q[r] = 0.f; }
            #pragma unroll 8
            for (int e = 0; e < 32; e++) {
                const float w1e  = sm[OFF_W1 + e * 32 + lane];
                const float w2e  = sm[OFF_W2 + e * 32 + lane];
                const float w34e = sm[OFF_W34 + e * 8 + la8];
                #pragma unroll
                for (int r = 0; r < 4; r++) {
                    const float he = __shfl_sync(0xffffffffu, h[r], e);
                    g1[r] = fmaf(he, w1e, g1[r]);
                    g2[r] = fmaf(he, w2e, g2[r]);
                    q[r]  = fmaf(he, w34e, q[r]);
                }
            }
            #pragma unroll
            for (int r = 0; r < 4; r++) g1[r] = fmaxf(g1[r], 0.f);

            // ---- wait for streamer's ys, then epilogue ----
            while (vflg[k] == 0) { __nanosleep(100); }
            __threadfence_block();
            const float* ysrc = sm + OFF_YS + k * 20;

            #pragma unroll
            for (int r = 0; r < 4; r++) {
                const int row = row0 + r;
                float ysr[NNv];
                #pragma unroll
                for (int n = 0; n < NNv; n++) ysr[n] = ysrc[r * 5 + n];

                float sc[NNv];
                #pragma unroll
                for (int n = 0; n < NNv; n++)
                    sc[n] = warpsum(g1[r] * fmaxf(fmaf(ysr[n], g2[r], b2v), 0.0f));

                float m = sc[0];
                #pragma unroll
                for (int n = 1; n < NNv; n++) m = fmaxf(m, sc[n]);
                float att[NNv], denom = 0.0f;
                #pragma unroll
                for (int n = 0; n < NNv; n++) { att[n] = __expf(sc[n] - m); denom += att[n]; }
                const float inv = 1.0f / denom;
                float sv = 0.0f;
                #pragma unroll
                for (int n = 0; n < NNv; n++) { att[n] *= inv; sv = fmaf(att[n], ysr[n], sv); }

                if (lane < NACTv)
                    out[(size_t)row * NACTv + lane] = fmaf(sv, q[r], b34pv);

                float av = 0.0f;
                #pragma unroll
                for (int n = 0; n < NNv; n++) if (lane == n) av = att[n];
                if (lane < NNv)
                    out[(size_t)ROWS * NACTv + (size_t)row * NNv + lane] = av;
            }
        }
    }
}

// ---------------------------------------------------------------------------
extern "C" void kernel_launch(void* const* d_in, const int* in_sizes, int n_in,
                              void* d_out, int out_size)
{
    const float* x   = (const float*)d_in[0];
    const float* y   = (const float*)d_in[1];
    const float* We0 = (const float*)d_in[2];
    const float* be0 = (const float*)d_in[3];
    const float* We1 = (const float*)d_in[4];
    const float* be1 = (const float*)d_in[5];
    const float* W1  = (const float*)d_in[6];
    const float* b1  = (const float*)d_in[7];
    const float* W2  = (const float*)d_in[8];
    const float* b2  = (const float*)d_in[9];
    const float* W3  = (const float*)d_in[10];
    const float* b3  = (const float*)d_in[11];
    const float* W4  = (const float*)d_in[12];
    const float* b4  = (const float*)d_in[13];
    const float* Wp  = (const float*)d_in[14];
    const float* bp  = (const float*)d_in[15];
    float* out = (float*)d_out;

    cudaFuncSetAttribute(fused_kernel, cudaFuncAttributeMaxDynamicSharedMemorySize, SMEM_BYTES);

    fused_kernel<<<GRID, NTHREADS, SMEM_BYTES>>>(
        x, y, We0, be0, We1, be1, W1, b1, W2, b2, W3, b3, W4, b4, Wp, bp, out);
}

// round 13
// speedup vs baseline: 1.0687x; 1.0687x over previous
#include <cuda_runtime.h>
#include <cstdint>

// Problem constants
#define NNv 5
#define NACTv 8
#define ROWS 32768
#define CHUNKS 8192               // chunks of 4 rows
#define ROW_F 5120                // floats per (b,j) row of y

#define NTHREADS 640              // 20 warps: 14 streamers + 6 MLP/epilogue producers
#define NSTREAM 14
#define NMLP 6
#define GRID 152

// smem layout, offsets in floats
#define OFF_WE0   0          // 128*128 = 16384
#define OFF_WE1   16384      // 128*32  = 4096
#define OFF_W1    20480      // 32*32
#define OFF_W2    21504
#define OFF_W3    22528
#define OFF_W4P   23552      // [8][32] fused W4@Wp
#define OFF_W34   23808      // [32][8] (W3 @ W4p^T)
#define OFF_BE0   24064      // 128
#define OFF_BE1   24192      // 32
#define OFF_B1    24224
#define OFF_B2    24256
#define OFF_B3    24288
#define OFF_B4P   24320      // 8 (b4@Wp+bp), pad 32
#define OFF_B34P  24352      // 8, pad 32
#define OFF_YS    24384      // 224 row-slots * 5 floats = 1120
#define OFF_YSFLG 25504      // 224 ints
#define OFF_XBUF  25728      // 6 mlp warps * 512 = 3072
#define OFF_CTR   28800      // 2 ints (streamer counter, producer counter)
#define SMEM_FLOATS 28808
#define SMEM_BYTES (SMEM_FLOATS * 4)   // ~115.2 KB

__device__ __forceinline__ float warpsum(float v) {
    v += __shfl_xor_sync(0xffffffffu, v, 16);
    v += __shfl_xor_sync(0xffffffffu, v, 8);
    v += __shfl_xor_sync(0xffffffffu, v, 4);
    v += __shfl_xor_sync(0xffffffffu, v, 2);
    v += __shfl_xor_sync(0xffffffffu, v, 1);
    return v;
}

__device__ __forceinline__ void fma4(float4& a, float s, const float4& w) {
    a.x = fmaf(s, w.x, a.x);
    a.y = fmaf(s, w.y, a.y);
    a.z = fmaf(s, w.z, a.z);
    a.w = fmaf(s, w.w, a.w);
}

__device__ __forceinline__ float r4(const float4& v) {
    return (v.x + v.y) + (v.z + v.w);
}

__global__ __launch_bounds__(NTHREADS, 1) void fused_kernel(
    const float* __restrict__ x,
    const float* __restrict__ y,
    const float* __restrict__ We0, const float* __restrict__ be0,
    const float* __restrict__ We1, const float* __restrict__ be1,
    const float* __restrict__ W1, const float* __restrict__ b1,
    const float* __restrict__ W2, const float* __restrict__ b2,
    const float* __restrict__ W3, const float* __restrict__ b3,
    const float* __restrict__ W4, const float* __restrict__ b4,
    const float* __restrict__ Wp, const float* __restrict__ bp,
    float* __restrict__ out)
{
    extern __shared__ float sm[];
    const int tid  = threadIdx.x;
    const int lane = tid & 31;
    const int w    = tid >> 5;
    const int b    = blockIdx.x;
    // chunks owned by this block: gchunk = b + GRID*k, k in [0, kcnt)
    const int kcnt = (CHUNKS - b + GRID - 1) / GRID;   // 53 or 54
    const int nrows = kcnt * 4;

    // ---- stage A: weights into smem + first-level fusions ----
    for (int i = tid; i < 16384; i += NTHREADS) sm[OFF_WE0 + i] = We0[i];
    for (int i = tid; i < 4096;  i += NTHREADS) sm[OFF_WE1 + i] = We1[i];
    for (int i = tid; i < 1024;  i += NTHREADS) {
        sm[OFF_W1 + i] = W1[i];
        sm[OFF_W2 + i] = W2[i];
        sm[OFF_W3 + i] = W3[i];
    }
    if (tid < 256) {
        const int a = tid >> 5, e = tid & 31;
        float acc = 0.f;
        #pragma unroll 8
        for (int k = 0; k < 32; k++)
            acc = fmaf(W4[e * 32 + k], Wp[k * NACTv + a], acc);
        sm[OFF_W4P + a * 32 + e] = acc;
    }
    if (tid < 128) sm[OFF_BE0 + tid] = be0[tid];
    if (tid < 32) {
        sm[OFF_BE1 + tid] = be1[tid];
        sm[OFF_B1 + tid] = b1[tid];
        sm[OFF_B2 + tid] = b2[tid];
        sm[OFF_B3 + tid] = b3[tid];
        if (tid < 8) {
            float acc = bp[tid];
            #pragma unroll 8
            for (int k = 0; k < 32; k++)
                acc = fmaf(b4[k], Wp[k * NACTv + tid], acc);
            sm[OFF_B4P + tid] = acc;
        }
    }
    int* ysflg = (int*)(sm + OFF_YSFLG);
    if (tid < 224) ysflg[tid] = 0;
    int* ctr = (int*)(sm + OFF_CTR);
    if (tid < 2) ctr[tid] = 0;
    __syncthreads();

    // ---- stage B: second-level fusions ----
    if (tid < 256) {
        const int e = tid >> 3, a = tid & 7;
        float acc = 0.f;
        #pragma unroll 8
        for (int d = 0; d < 32; d++)
            acc = fmaf(sm[OFF_W3 + e * 32 + d], sm[OFF_W4P + a * 32 + d], acc);
        sm[OFF_W34 + e * 8 + a] = acc;
    }
    if (tid < 8) {
        float acc = sm[OFF_B4P + tid];
        #pragma unroll 8
        for (int d = 0; d < 32; d++)
            acc = fmaf(sm[OFF_B3 + d], sm[OFF_W4P + tid * 32 + d], acc);
        sm[OFF_B34P + tid] = acc;
    }
    __syncthreads();

    volatile int* vflg = (volatile int*)ysflg;

    if (w < NSTREAM) {
        // ====== STREAMER warps: steal 1-row units, pure streaming, no waits ======
        for (;;) {
            int u;
            if (lane == 0) u = atomicAdd(&ctr[0], 1);
            u = __shfl_sync(0xffffffffu, u, 0);
            if (u >= nrows) break;

            const int k = u >> 2, r = u & 3;
            const int grow = (b + GRID * k) * 4 + r;

            // 40 loads in 5 independent chains (plain loads, no .cs)
            const float4* yb = (const float4*)(y + (size_t)grow * ROW_F) + lane;
            float a0 = 0.f, a1 = 0.f, a2 = 0.f, a3 = 0.f, a4 = 0.f;
            #pragma unroll
            for (int i = 0; i < 8; i++) {
                a0 += r4(yb[0 * 256 + i * 32]);
                a1 += r4(yb[1 * 256 + i * 32]);
                a2 += r4(yb[2 * 256 + i * 32]);
                a3 += r4(yb[3 * 256 + i * 32]);
                a4 += r4(yb[4 * 256 + i * 32]);
            }
            a0 = warpsum(a0);
            a1 = warpsum(a1);
            a2 = warpsum(a2);
            a3 = warpsum(a3);
            a4 = warpsum(a4);
            if (lane == 0) {
                float* dst = sm + OFF_YS + u * 5;
                dst[0] = a0; dst[1] = a1; dst[2] = a2; dst[3] = a3; dst[4] = a4;
                __threadfence_block();
                vflg[u] = 1;
            }
        }
    } else {
        // ===== PRODUCER warps: steal 4-row chunks, MLP + epilogue =====
        const int mw = w - NSTREAM;
        const float4* We0s4 = (const float4*)(sm + OFF_WE0);
        const float4* be0s4 = (const float4*)(sm + OFF_BE0);
        float4* xb4 = (float4*)(sm + OFF_XBUF) + mw * 128;
        const float b1v  = sm[OFF_B1 + lane];
        const float b2v  = sm[OFF_B2 + lane];
        const float be1v = sm[OFF_BE1 + lane];
        const float b34pv = sm[OFF_B34P + (lane & 7)];
        const int la8 = lane & 7;

        for (;;) {
            int k;
            if (lane == 0) k = atomicAdd(&ctr[1], 1);
            k = __shfl_sync(0xffffffffu, k, 0);
            if (k >= kcnt) break;
            const int row0 = (b + GRID * k) * 4;

            // stage x
            #pragma unroll
            for (int r = 0; r < 4; r++)
                xb4[r * 32 + lane] = ((const float4*)(x))[(size_t)(row0 + r) * 32 + lane];
            __syncwarp();

            // layer 0
            float4 acc0 = be0s4[lane], acc1 = acc0, acc2 = acc0, acc3 = acc0;
            #pragma unroll 8
            for (int k4 = 0; k4 < 32; k4++) {
                float4 w0 = We0s4[(k4 * 4 + 0) * 32 + lane];
                float4 w1 = We0s4[(k4 * 4 + 1) * 32 + lane];
                float4 w2 = We0s4[(k4 * 4 + 2) * 32 + lane];
                float4 w3 = We0s4[(k4 * 4 + 3) * 32 + lane];
                float4 xk;
                xk = xb4[0 * 32 + k4];
                fma4(acc0, xk.x, w0); fma4(acc0, xk.y, w1); fma4(acc0, xk.z, w2); fma4(acc0, xk.w, w3);
                xk = xb4[1 * 32 + k4];
                fma4(acc1, xk.x, w0); fma4(acc1, xk.y, w1); fma4(acc1, xk.z, w2); fma4(acc1, xk.w, w3);
                xk = xb4[2 * 32 + k4];
                fma4(acc2, xk.x, w0); fma4(acc2, xk.y, w1); fma4(acc2, xk.z, w2); fma4(acc2, xk.w, w3);
                xk = xb4[3 * 32 + k4];
                fma4(acc3, xk.x, w0); fma4(acc3, xk.y, w1); fma4(acc3, xk.z, w2); fma4(acc3, xk.w, w3);
            }
            __syncwarp();
            acc0.x = fmaxf(acc0.x, 0.f); acc0.y = fmaxf(acc0.y, 0.f); acc0.z = fmaxf(acc0.z, 0.f); acc0.w = fmaxf(acc0.w, 0.f);
            acc1.x = fmaxf(acc1.x, 0.f); acc1.y = fmaxf(acc1.y, 0.f); acc1.z = fmaxf(acc1.z, 0.f); acc1.w = fmaxf(acc1.w, 0.f);
            acc2.x = fmaxf(acc2.x, 0.f); acc2.y = fmaxf(acc2.y, 0.f); acc2.z = fmaxf(acc2.z, 0.f); acc2.w = fmaxf(acc2.w, 0.f);
            acc3.x = fmaxf(acc3.x, 0.f); acc3.y = fmaxf(acc3.y, 0.f); acc3.z = fmaxf(acc3.z, 0.f); acc3.w = fmaxf(acc3.w, 0.f);
            xb4[0 * 32 + lane] = acc0;
            xb4[1 * 32 + lane] = acc1;
            xb4[2 * 32 + lane] = acc2;
            xb4[3 * 32 + lane] = acc3;
            __syncwarp();

            // layer 1
            float a1_0 = be1v, a1_1 = be1v, a1_2 = be1v, a1_3 = be1v;
            #pragma unroll 8
            for (int k4 = 0; k4 < 32; k4++) {
                float w0 = sm[OFF_WE1 + (k4 * 4 + 0) * 32 + lane];
                float w1 = sm[OFF_WE1 + (k4 * 4 + 1) * 32 + lane];
                float w2 = sm[OFF_WE1 + (k4 * 4 + 2) * 32 + lane];
                float w3 = sm[OFF_WE1 + (k4 * 4 + 3) * 32 + lane];
                float4 hk;
                hk = xb4[0 * 32 + k4];
                a1_0 = fmaf(hk.x, w0, a1_0); a1_0 = fmaf(hk.y, w1, a1_0); a1_0 = fmaf(hk.z, w2, a1_0); a1_0 = fmaf(hk.w, w3, a1_0);
                hk = xb4[1 * 32 + k4];
                a1_1 = fmaf(hk.x, w0, a1_1); a1_1 = fmaf(hk.y, w1, a1_1); a1_1 = fmaf(hk.z, w2, a1_1); a1_1 = fmaf(hk.w, w3, a1_1);
                hk = xb4[2 * 32 + k4];
                a1_2 = fmaf(hk.x, w0, a1_2); a1_2 = fmaf(hk.y, w1, a1_2); a1_2 = fmaf(hk.z, w2, a1_2); a1_2 = fmaf(hk.w, w3, a1_2);
                hk = xb4[3 * 32 + k4];
                a1_3 = fmaf(hk.x, w0, a1_3); a1_3 = fmaf(hk.y, w1, a1_3); a1_3 = fmaf(hk.z, w2, a1_3); a1_3 = fmaf(hk.w, w3, a1_3);
            }
            float h[4];
            h[0] = fmaxf(a1_0, 0.f); h[1] = fmaxf(a1_1, 0.f);
            h[2] = fmaxf(a1_2, 0.f); h[3] = fmaxf(a1_3, 0.f);

            // g1/g2 per lane-dim; q on lanes 0..7
            float g1[4], g2[4], q[4];
            #pragma unroll
            for (int r = 0; r < 4; r++) { g1[r] = b1v; g2[r] = 0.f; q[r] = 0.f; }
            #pragma unroll 8
            for (int e = 0; e < 32; e++) {
                const float w1e  = sm[OFF_W1 + e * 32 + lane];
                const float w2e  = sm[OFF_W2 + e * 32 + lane];
                const float w34e = sm[OFF_W34 + e * 8 + la8];
                #pragma unroll
                for (int r = 0; r < 4; r++) {
                    const float he = __shfl_sync(0xffffffffu, h[r], e);
                    g1[r] = fmaf(he, w1e, g1[r]);
                    g2[r] = fmaf(he, w2e, g2[r]);
                    q[r]  = fmaf(he, w34e, q[r]);
                }
            }
            #pragma unroll
            for (int r = 0; r < 4; r++) g1[r] = fmaxf(g1[r], 0.f);

            // ---- per-row: wait for streamer ys, then epilogue ----
            #pragma unroll 1
            for (int r = 0; r < 4; r++) {
                const int u = k * 4 + r;
                const int row = row0 + r;

                while (vflg[u] == 0) { __nanosleep(100); }
                __threadfence_block();
                const float* ysrc = sm + OFF_YS + u * 5;
                float ysr[NNv];
                #pragma unroll
                for (int n = 0; n < NNv; n++) ysr[n] = ysrc[n];

                float sc[NNv];
                #pragma unroll
                for (int n = 0; n < NNv; n++)
                    sc[n] = warpsum(g1[r] * fmaxf(fmaf(ysr[n], g2[r], b2v), 0.0f));

                float m = sc[0];
                #pragma unroll
                for (int n = 1; n < NNv; n++) m = fmaxf(m, sc[n]);
                float att[NNv], denom = 0.0f;
                #pragma unroll
                for (int n = 0; n < NNv; n++) { att[n] = __expf(sc[n] - m); denom += att[n]; }
                const float inv = 1.0f / denom;
                float sv = 0.0f;
                #pragma unroll
                for (int n = 0; n < NNv; n++) { att[n] *= inv; sv = fmaf(att[n], ysr[n], sv); }

                if (lane < NACTv)
                    out[(size_t)row * NACTv + lane] = fmaf(sv, q[r], b34pv);

                float av = 0.0f;
                #pragma unroll
                for (int n = 0; n < NNv; n++) if (lane == n) av = att[n];
                if (lane < NNv)
                    out[(size_t)ROWS * NACTv + (size_t)row * NNv + lane] = av;
            }
        }
    }
}

// ---------------------------------------------------------------------------
extern "C" void kernel_launch(void* const* d_in, const int* in_sizes, int n_in,
                              void* d_out, int out_size)
{
    const float* x   = (const float*)d_in[0];
    const float* y   = (const float*)d_in[1];
    const float* We0 = (const float*)d_in[2];
    const float* be0 = (const float*)d_in[3];
    const float* We1 = (const float*)d_in[4];
    const float* be1 = (const float*)d_in[5];
    const float* W1  = (const float*)d_in[6];
    const float* b1  = (const float*)d_in[7];
    const float* W2  = (const float*)d_in[8];
    const float* b2  = (const float*)d_in[9];
    const float* W3  = (const float*)d_in[10];
    const float* b3  = (const float*)d_in[11];
    const float* W4  = (const float*)d_in[12];
    const float* b4  = (const float*)d_in[13];
    const float* Wp  = (const float*)d_in[14];
    const float* bp  = (const float*)d_in[15];
    float* out = (float*)d_out;

    cudaFuncSetAttribute(fused_kernel, cudaFuncAttributeMaxDynamicSharedMemorySize, SMEM_BYTES);

    fused_kernel<<<GRID, NTHREADS, SMEM_BYTES>>>(
        x, y, We0, be0, We1, be1, W1, b1, W2, b2, W3, b3, W4, b4, Wp, bp, out);
}